// round 11
// baseline (speedup 1.0000x reference)
#include <cuda_runtime.h>
#include <cstdint>
#include <cstddef>

#define BB 64
#define SS 2048
#define DIN 512
#define HH 1024
#define SPLITS 8                       // tiles per batch; 512 tiles total
#define NTILES (BB * SPLITS)
#define ROWS_PER_TILE (SS / SPLITS)    // 256
#define NWARP 16
#define NB 16                          // rows per block
#define CDEPTH 3                       // cbuf slots (prefetch distance 2)
#define KSPLIT 16                      // gemm k-chunks
#define KC 32
#define HC 64

// ---------------- scratch (no allocations allowed) ----------------
__device__ __align__(16) float g_x[BB * HH];            // inp@W + b
__device__ __align__(16) float g_xpart[KSPLIT * BB * HH];
__device__ unsigned char  g_mask[BB * SS];              // canonical mask (1 = masked)
__device__ float          g_p[BB * SS];                 // exp(score); 0 where masked
__device__ __align__(16) float g_acc[NTILES * HH];      // tile partial weighted sums
__device__ float          g_l[NTILES];                  // tile partial sum-of-exp
__device__ unsigned       g_ticket;                     // persistent work queue
__device__ unsigned       g_bdone[BB];                  // per-batch tile completion

// ---------------- helpers ----------------
__device__ __forceinline__ float tanh_fast(float x) {
    float y;
    asm("tanh.approx.f32 %0, %1;" : "=f"(y) : "f"(x));
    return y;
}

// ---------------- kernel 0: gemm partials (256 CTAs) + mask (64 CTAs) -------
__global__ __launch_bounds__(256) void prologue_kernel(const float* __restrict__ inp,
                                                       const float* __restrict__ Wm,
                                                       const void*  __restrict__ mraw) {
    __shared__ float Ws[KC][HC];   // 8 KB
    __shared__ float Is[KC][BB];   // 8 KB (k-major)
    int t   = threadIdx.x;
    int blk = blockIdx.x;

    if (blk < 256) {                               // ---- GEMM partials ----
        int kc = blk >> 4, hcb = blk & 15;
        int k0 = kc * KC, h0 = hcb * HC;

        for (int i = t; i < KC * HC / 4; i += 256) {
            int k = i >> 4, hj = i & 15;
            *(float4*)&Ws[k][hj * 4] =
                *(const float4*)&Wm[(size_t)(k0 + k) * HH + h0 + hj * 4];
        }
        for (int i = t; i < BB * KC / 4; i += 256) {
            int b = i >> 3, j = i & 7;
            float4 p = *(const float4*)&inp[b * DIN + k0 + j * 4];
            Is[j * 4 + 0][b] = p.x;
            Is[j * 4 + 1][b] = p.y;
            Is[j * 4 + 2][b] = p.z;
            Is[j * 4 + 3][b] = p.w;
        }
        __syncthreads();

        int ty = t >> 4, tx = t & 15;          // 4 batches x 4 cols / thread
        float4 a0 = {0,0,0,0}, a1 = {0,0,0,0}, a2 = {0,0,0,0}, a3 = {0,0,0,0};
#pragma unroll 8
        for (int k = 0; k < KC; k++) {
            float4 ib = *(const float4*)&Is[k][ty * 4];
            float4 wv = *(const float4*)&Ws[k][tx * 4];
            a0.x = fmaf(ib.x, wv.x, a0.x); a0.y = fmaf(ib.x, wv.y, a0.y);
            a0.z = fmaf(ib.x, wv.z, a0.z); a0.w = fmaf(ib.x, wv.w, a0.w);
            a1.x = fmaf(ib.y, wv.x, a1.x); a1.y = fmaf(ib.y, wv.y, a1.y);
            a1.z = fmaf(ib.y, wv.z, a1.z); a1.w = fmaf(ib.y, wv.w, a1.w);
            a2.x = fmaf(ib.z, wv.x, a2.x); a2.y = fmaf(ib.z, wv.y, a2.y);
            a2.z = fmaf(ib.z, wv.z, a2.z); a2.w = fmaf(ib.z, wv.w, a2.w);
            a3.x = fmaf(ib.w, wv.x, a3.x); a3.y = fmaf(ib.w, wv.y, a3.y);
            a3.z = fmaf(ib.w, wv.z, a3.z); a3.w = fmaf(ib.w, wv.w, a3.w);
        }
        float* outb = g_xpart + (size_t)kc * (BB * HH) + h0 + tx * 4;
        *(float4*)&outb[(ty * 4 + 0) * HH] = a0;
        *(float4*)&outb[(ty * 4 + 1) * HH] = a1;
        *(float4*)&outb[(ty * 4 + 2) * HH] = a2;
        *(float4*)&outb[(ty * 4 + 3) * HH] = a3;
    } else {                                    // ---- mask canonicalize ----
        const unsigned* wds = (const unsigned*)mraw;
        int notInt = 0, notFloat = 0;
        for (int i = t; i < 1024; i += 256) {
            unsigned x = wds[i];
            notInt   |= (x > 1u);
            notFloat |= (x != 0u && x != 0x3F800000u);
        }
        notInt   = __syncthreads_or(notInt);
        notFloat = __syncthreads_or(notFloat);
        int mode = notInt ? (notFloat ? 2 : 1) : 0;  // 0:int32 1:float32 2:bytes

        int base = (blk - 256) * 2048;
        for (int i = base + t; i < base + 2048; i += 256) {
            unsigned char v;
            if (mode == 0)      v = (((const int*)mraw)[i] != 0);
            else if (mode == 1) v = (((const float*)mraw)[i] != 0.0f);
            else                v = (((const unsigned char*)mraw)[i] != 0);
            g_mask[i] = v;
        }
    }
}

// ---------------- kernel 1: reduce gemm partials + bias, reset counters -----
__global__ __launch_bounds__(128) void xreduce_kernel(const float* __restrict__ bias) {
    int i = blockIdx.x * 128 + threadIdx.x;     // float4 index, 16384 total
    if (i == 0) g_ticket = 0;
    if (i < BB) g_bdone[i] = 0;
    float4 s = *(const float4*)&bias[(i & 255) * 4];
    const float4* xp = (const float4*)g_xpart;
#pragma unroll
    for (int kc = 0; kc < KSPLIT; kc++) {
        float4 p = xp[kc * (BB * HH / 4) + i];
        s.x += p.x; s.y += p.y; s.z += p.z; s.w += p.w;
    }
    ((float4*)g_x)[i] = s;
}

// ---------------- kernel 2: two-phase blocked pass -------------------------
// Per tile (256 rows): compact unmasked rows; process 16-row blocks.
// Phase A: warp w -> score of block-row w (x, v in regs), p to smem+global.
// Phase B: thread t -> H-columns {2t, 2t+1}, acc2 += p[s] * c[s]  (no x-warp
// reduction needed anywhere; tile output is one float2 store per thread).
__device__ __forceinline__ void prefetch_block(const float* cb, int blk, int n,
                                               unsigned cbuf_u32, int slot,
                                               int w, int ln, const int* s_idx) {
    int k = blk * NB + w;
    if (k < n) {
        const float* src = cb + (size_t)s_idx[k] * HH + ln * 4;
        unsigned dst = cbuf_u32 + (slot * NB + w) * (HH * 4) + ln * 16;
#pragma unroll
        for (int i = 0; i < 8; i++)
            asm volatile("cp.async.cg.shared.global [%0], [%1], 16;"
                         :: "r"(dst + i * 512), "l"(src + i * 128) : "memory");
    }
    asm volatile("cp.async.commit_group;" ::: "memory");
}

__global__ __launch_bounds__(512, 1) void pass1_kernel(const float* __restrict__ ctx,
                                                       const float* __restrict__ v,
                                                       float* __restrict__ out_applied,
                                                       float* __restrict__ out_w) {
    extern __shared__ float cbuf[];    // CDEPTH * NB * HH floats = 192 KB

    __shared__ float    ps[CDEPTH][NB];
    __shared__ int      s_idx[ROWS_PER_TILE];
    __shared__ int      s_wcnt[8];
    __shared__ float    s_l[NWARP];
    __shared__ unsigned s_tile;
    __shared__ int      s_last;

    int t  = threadIdx.x;
    int w  = t >> 5;
    int ln = t & 31;

    float4 vv[8];
    const float4* vr = (const float4*)v;
#pragma unroll
    for (int j = 0; j < 8; j++) vv[j] = __ldg(&vr[j * 32 + ln]);

    unsigned cbuf_u32 = (unsigned)__cvta_generic_to_shared(cbuf);

    for (;;) {
        if (t == 0) s_tile = atomicAdd(&g_ticket, 1u);
        __syncthreads();               // also orders prior tile's smem reuse
        unsigned tile = s_tile;
        if (tile >= NTILES) break;

        int b  = tile >> 3;            // SPLITS = 8
        int sp = tile & (SPLITS - 1);
        int rowbase = b * SS + sp * ROWS_PER_TILE;

        // x for this batch -> registers (L2-hot, once per tile)
        float4 xv[8];
        const float4* xr = (const float4*)(g_x + b * HH);
#pragma unroll
        for (int j = 0; j < 8; j++) xv[j] = __ldg(&xr[j * 32 + ln]);

        // ---- compact unmasked row indices (deterministic order) ----
        unsigned char mk = 1;
        if (t < ROWS_PER_TILE) mk = g_mask[rowbase + t];
        unsigned bits = __ballot_sync(0xffffffffu, mk == 0);
        if (t < ROWS_PER_TILE && mk) g_p[rowbase + t] = 0.0f;   // masked -> 0
        if (w < 8 && ln == 0) s_wcnt[w] = __popc(bits);
        __syncthreads();
        int n = 0;
#pragma unroll
        for (int i = 0; i < 8; i++) n += s_wcnt[i];
        if (t < ROWS_PER_TILE && !mk) {
            int basew = 0;
#pragma unroll
            for (int i = 0; i < 8; i++) if (i < w) basew += s_wcnt[i];
            s_idx[basew + __popc(bits & ((1u << ln) - 1u))] = t;
        }
        __syncthreads();

        int nblk = (n + NB - 1) >> 4;
        float2 acc2 = make_float2(0.f, 0.f);
        float  lw = 0.f;

        const float* cb = ctx + (size_t)rowbase * HH;
        prefetch_block(cb, 0, n, cbuf_u32, 0, w, ln, s_idx);
        prefetch_block(cb, 1, n, cbuf_u32, 1, w, ln, s_idx);

        int slot = 0;
        for (int i = 0; i < nblk; i++) {
            asm volatile("cp.async.wait_group 1;" ::: "memory");
            __syncthreads();           // block i visible to all; prior B done

            int slot2 = slot + 2; if (slot2 >= CDEPTH) slot2 -= CDEPTH;
            prefetch_block(cb, i + 2, n, cbuf_u32, slot2, w, ln, s_idx);

            // ---- Phase A: warp w scores block-row w ----
            int k = i * NB + w;
            float p = 0.f;
            if (k < n) {
                const float* crow = cbuf + (slot * NB + w) * HH;
                float p0 = 0.f, p1 = 0.f, p2 = 0.f, p3 = 0.f;
#pragma unroll
                for (int j = 0; j < 8; j++) {
                    float4 c  = *(const float4*)&crow[j * 128 + ln * 4];
                    float4 vg = vv[j];
                    p0 = fmaf(tanh_fast(xv[j].x + c.x), vg.x, p0);
                    p1 = fmaf(tanh_fast(xv[j].y + c.y), vg.y, p1);
                    p2 = fmaf(tanh_fast(xv[j].z + c.z), vg.z, p2);
                    p3 = fmaf(tanh_fast(xv[j].w + c.w), vg.w, p3);
                }
                float part = (p0 + p1) + (p2 + p3);
#pragma unroll
                for (int off = 16; off; off >>= 1)
                    part += __shfl_xor_sync(0xffffffffu, part, off);
                p = __expf(part);      // fixed reference M=0: |score| < 40
                if (ln == 0) g_p[rowbase + s_idx[k]] = p;
            }
            if (ln == 0) ps[slot][w] = p;
            lw += p;
            __syncthreads();           // ps + (cbuf stable) for Phase B

            // ---- Phase B: thread t accumulates H-cols {2t, 2t+1} ----
            const float* cb0 = cbuf + slot * (NB * HH) + t * 2;
            int rb = n - i * NB;
            if (rb >= NB) {
#pragma unroll
                for (int s = 0; s < NB; s++) {
                    float pp = ps[slot][s];
                    float2 c2 = *(const float2*)&cb0[s * HH];
                    acc2.x = fmaf(c2.x, pp, acc2.x);
                    acc2.y = fmaf(c2.y, pp, acc2.y);
                }
            } else {
                for (int s = 0; s < rb; s++) {
                    float pp = ps[slot][s];
                    float2 c2 = *(const float2*)&cb0[s * HH];
                    acc2.x = fmaf(c2.x, pp, acc2.x);
                    acc2.y = fmaf(c2.y, pp, acc2.y);
                }
            }
            slot = slot + 1; if (slot >= CDEPTH) slot -= CDEPTH;
        }
        asm volatile("cp.async.wait_group 0;" ::: "memory");

        // ---- tile epilogue: no cross-warp acc reduce needed ----
        if (ln == 0) s_l[w] = lw;
        __syncthreads();
        *(float2*)&g_acc[(size_t)tile * HH + t * 2] = acc2;
        float L = 0.f;
#pragma unroll
        for (int i = 0; i < NWARP; i++) L += s_l[i];
        if (t == 0) g_l[tile] = L;

        // ---- last tile of this batch? finalize the batch here ----
        __threadfence();
        if (t == 0) {
            unsigned old = atomicAdd(&g_bdone[b], 1u);
            s_last = (old == SPLITS - 1);
        }
        __syncthreads();
        if (s_last) {
            float Lb = 0.f;
#pragma unroll
            for (int i = 0; i < SPLITS; i++) Lb += __ldcg(&g_l[b * SPLITS + i]);
            float invL = 1.0f / Lb;
#pragma unroll
            for (int r = 0; r < 2; r++) {
                int h = t + r * 512;
                float s = 0.f;
#pragma unroll
                for (int i = 0; i < SPLITS; i++)
                    s += __ldcg(&g_acc[(size_t)(b * SPLITS + i) * HH + h]);
                out_applied[b * HH + h] = s * invL;
            }
#pragma unroll
            for (int r = 0; r < 4; r++) {
                int si = t + r * 512;
                out_w[b * SS + si] = __ldcg(&g_p[b * SS + si]) * invL;
            }
        }
        // top-of-loop __syncthreads orders smem reuse for the next tile
    }
}

// ---------------- launch ----------------
extern "C" void kernel_launch(void* const* d_in, const int* in_sizes, int n_in,
                              void* d_out, int out_size) {
    const float* inp  = (const float*)d_in[0];
    // d_in[1] = hidden (unused by the reference computation)
    const float* ctx  = (const float*)d_in[2];
    const void*  mask = d_in[3];
    const float* Wm   = (const float*)d_in[4];
    const float* bias = (const float*)d_in[5];
    const float* v    = (const float*)d_in[6];
    float* out = (float*)d_out;

    const int dyn_smem = (CDEPTH * NB * HH) * (int)sizeof(float);  // 196608
    cudaFuncSetAttribute(pass1_kernel,
                         cudaFuncAttributeMaxDynamicSharedMemorySize, dyn_smem);

    prologue_kernel<<<320, 256>>>(inp, Wm, mask);
    xreduce_kernel<<<128, 128>>>(bias);
    pass1_kernel<<<152, 512, dyn_smem>>>(ctx, v, out, out + BB * HH);
}

// round 12
// speedup vs baseline: 1.2071x; 1.2071x over previous
#include <cuda_runtime.h>
#include <cstdint>
#include <cstddef>

#define BB 64
#define SS 2048
#define DIN 512
#define HH 1024
#define SPLITS 16                      // tiles per batch; 1024 tiles total
#define NTILES (BB * SPLITS)
#define ROWS_PER_TILE (SS / SPLITS)    // 128
#define NWARP 16
#define RING_DEPTH 3
#define KSPLIT 16                      // gemm k-chunks
#define KC 32
#define HC 64

#define NEG_INF __int_as_float(0xff800000)

// ---------------- scratch (no allocations allowed) ----------------
__device__ __align__(16) float g_x[BB * HH];            // inp@W + b
__device__ __align__(16) float g_xpart[KSPLIT * BB * HH];
__device__ unsigned char  g_mask[BB * SS];              // canonical mask (1 = masked)
__device__ float          g_score[BB * SS];             // raw scores (-inf where masked)
__device__ __align__(16) float g_acc[NTILES * HH];      // tile partial weighted sums
__device__ float          g_l[NTILES];                  // tile partial sum-of-exp
__device__ unsigned       g_ticket;                     // persistent work queue
__device__ unsigned       g_bdone[BB];                  // per-batch tile completion

// ---------------- helpers ----------------
__device__ __forceinline__ float tanh_fast(float x) {
    float y;
    asm("tanh.approx.f32 %0, %1;" : "=f"(y) : "f"(x));
    return y;
}

// ---------------- kernel 0: gemm partials (256 CTAs) + mask (64 CTAs) -------
__global__ __launch_bounds__(256) void prologue_kernel(const float* __restrict__ inp,
                                                       const float* __restrict__ Wm,
                                                       const void*  __restrict__ mraw) {
    __shared__ float Ws[KC][HC];   // 8 KB
    __shared__ float Is[KC][BB];   // 8 KB (k-major)
    int t   = threadIdx.x;
    int blk = blockIdx.x;

    if (blk < 256) {                               // ---- GEMM partials ----
        int kc = blk >> 4, hcb = blk & 15;
        int k0 = kc * KC, h0 = hcb * HC;

        for (int i = t; i < KC * HC / 4; i += 256) {
            int k = i >> 4, hj = i & 15;
            *(float4*)&Ws[k][hj * 4] =
                *(const float4*)&Wm[(size_t)(k0 + k) * HH + h0 + hj * 4];
        }
        for (int i = t; i < BB * KC / 4; i += 256) {
            int b = i >> 3, j = i & 7;
            float4 p = *(const float4*)&inp[b * DIN + k0 + j * 4];
            Is[j * 4 + 0][b] = p.x;
            Is[j * 4 + 1][b] = p.y;
            Is[j * 4 + 2][b] = p.z;
            Is[j * 4 + 3][b] = p.w;
        }
        __syncthreads();

        int ty = t >> 4, tx = t & 15;          // 4 batches x 4 cols / thread
        float4 a0 = {0,0,0,0}, a1 = {0,0,0,0}, a2 = {0,0,0,0}, a3 = {0,0,0,0};
#pragma unroll 8
        for (int k = 0; k < KC; k++) {
            float4 ib = *(const float4*)&Is[k][ty * 4];
            float4 wv = *(const float4*)&Ws[k][tx * 4];
            a0.x = fmaf(ib.x, wv.x, a0.x); a0.y = fmaf(ib.x, wv.y, a0.y);
            a0.z = fmaf(ib.x, wv.z, a0.z); a0.w = fmaf(ib.x, wv.w, a0.w);
            a1.x = fmaf(ib.y, wv.x, a1.x); a1.y = fmaf(ib.y, wv.y, a1.y);
            a1.z = fmaf(ib.y, wv.z, a1.z); a1.w = fmaf(ib.y, wv.w, a1.w);
            a2.x = fmaf(ib.z, wv.x, a2.x); a2.y = fmaf(ib.z, wv.y, a2.y);
            a2.z = fmaf(ib.z, wv.z, a2.z); a2.w = fmaf(ib.z, wv.w, a2.w);
            a3.x = fmaf(ib.w, wv.x, a3.x); a3.y = fmaf(ib.w, wv.y, a3.y);
            a3.z = fmaf(ib.w, wv.z, a3.z); a3.w = fmaf(ib.w, wv.w, a3.w);
        }
        float* outb = g_xpart + (size_t)kc * (BB * HH) + h0 + tx * 4;
        *(float4*)&outb[(ty * 4 + 0) * HH] = a0;
        *(float4*)&outb[(ty * 4 + 1) * HH] = a1;
        *(float4*)&outb[(ty * 4 + 2) * HH] = a2;
        *(float4*)&outb[(ty * 4 + 3) * HH] = a3;
    } else {                                    // ---- mask canonicalize ----
        const unsigned* wds = (const unsigned*)mraw;
        int notInt = 0, notFloat = 0;
        for (int i = t; i < 1024; i += 256) {
            unsigned x = wds[i];
            notInt   |= (x > 1u);
            notFloat |= (x != 0u && x != 0x3F800000u);
        }
        notInt   = __syncthreads_or(notInt);
        notFloat = __syncthreads_or(notFloat);
        int mode = notInt ? (notFloat ? 2 : 1) : 0;  // 0:int32 1:float32 2:bytes

        int base = (blk - 256) * 2048;
        for (int i = base + t; i < base + 2048; i += 256) {
            unsigned char v;
            if (mode == 0)      v = (((const int*)mraw)[i] != 0);
            else if (mode == 1) v = (((const float*)mraw)[i] != 0.0f);
            else                v = (((const unsigned char*)mraw)[i] != 0);
            g_mask[i] = v;
        }
    }
}

// ---------------- kernel 1: reduce gemm partials + bias, reset counters -----
__global__ __launch_bounds__(128) void xreduce_kernel(const float* __restrict__ bias) {
    int i = blockIdx.x * 128 + threadIdx.x;     // float4 index, 16384 total
    if (i == 0) g_ticket = 0;
    if (i < BB) g_bdone[i] = 0;
    float4 s = *(const float4*)&bias[(i & 255) * 4];
    const float4* xp = (const float4*)g_xpart;
#pragma unroll
    for (int kc = 0; kc < KSPLIT; kc++) {
        float4 p = xp[kc * (BB * HH / 4) + i];
        s.x += p.x; s.y += p.y; s.z += p.z; s.w += p.w;
    }
    ((float4*)g_x)[i] = s;
}

// ---------------- kernel 2: fused scores+exp-sum+weighted sum+finalize ------
__device__ __forceinline__ void issue_row(const float* cb, int k, int n,
                                          unsigned slot_u32, int ln,
                                          const int* s_idx) {
    if (k < n) {
        const float* src = cb + (size_t)s_idx[k] * HH + ln * 4;
        unsigned dst = slot_u32 + ln * 16;
#pragma unroll
        for (int i = 0; i < 8; i++)
            asm volatile("cp.async.cg.shared.global [%0], [%1], 16;"
                         :: "r"(dst + i * 512), "l"(src + i * 128) : "memory");
    }
    asm volatile("cp.async.commit_group;" ::: "memory");
}

__global__ __launch_bounds__(512, 1) void pass1_kernel(const float* __restrict__ ctx,
                                                       const float* __restrict__ v,
                                                       float* __restrict__ out_applied,
                                                       float* __restrict__ out_w) {
    extern __shared__ float dsm[];
    float* xs   = dsm;                 // HH floats
    float* ring = dsm + HH;            // NWARP * RING_DEPTH * HH floats

    __shared__ int      s_idx[ROWS_PER_TILE];
    __shared__ int      s_wcnt[4];
    __shared__ float    s_l[NWARP];
    __shared__ unsigned s_tile;
    __shared__ int      s_last;

    int t  = threadIdx.x;
    int w  = t >> 5;
    int ln = t & 31;

    float4 vv[8];
    const float4* vr = (const float4*)v;
#pragma unroll
    for (int j = 0; j < 8; j++) vv[j] = __ldg(&vr[j * 32 + ln]);

    float* myring = ring + w * (RING_DEPTH * HH);
    unsigned ring_u32 = (unsigned)__cvta_generic_to_shared(myring);

    for (;;) {
        if (t == 0) s_tile = atomicAdd(&g_ticket, 1u);
        __syncthreads();               // also orders prior tile's smem reuse
        unsigned tile = s_tile;
        if (tile >= NTILES) break;

        int b  = tile >> 4;            // SPLITS = 16
        int sp = tile & (SPLITS - 1);
        int rowbase = b * SS + sp * ROWS_PER_TILE;

        xs[t]       = g_x[b * HH + t];
        xs[t + 512] = g_x[b * HH + 512 + t];

        // ---- compact unmasked row indices (deterministic order) ----
        unsigned char mk = 1;
        if (t < ROWS_PER_TILE) mk = g_mask[rowbase + t];
        unsigned bits = __ballot_sync(0xffffffffu, mk == 0);
        if (t < ROWS_PER_TILE && mk) g_score[rowbase + t] = NEG_INF;
        if (w < 4 && ln == 0) s_wcnt[w] = __popc(bits);
        __syncthreads();
        int n = s_wcnt[0] + s_wcnt[1] + s_wcnt[2] + s_wcnt[3];
        if (t < ROWS_PER_TILE && !mk) {
            int basew = 0;
#pragma unroll
            for (int i = 0; i < 4; i++) if (i < w) basew += s_wcnt[i];
            s_idx[basew + __popc(bits & ((1u << ln) - 1u))] = t;
        }
        __syncthreads();

        // ---- per-warp row loop over compacted list ----
        float4 acc[8];
#pragma unroll
        for (int j = 0; j < 8; j++) acc[j] = make_float4(0.f, 0.f, 0.f, 0.f);
        float l = 0.f;

        const float* cb = ctx + (size_t)rowbase * HH;
        issue_row(cb, w,             n, ring_u32,          ln, s_idx);
        issue_row(cb, w + NWARP,     n, ring_u32 + HH * 4, ln, s_idx);
        issue_row(cb, w + 2 * NWARP, n, ring_u32 + HH * 8, ln, s_idx);
        int slot = 0;
        for (int k = w; k < n; k += NWARP) {
            asm volatile("cp.async.wait_group 2;" ::: "memory");
            const float* sp_ = myring + slot * HH;

            float part = 0.f;
#pragma unroll
            for (int j = 0; j < 8; j++) {
                float4 c  = *(const float4*)&sp_[j * 128 + ln * 4];
                float4 xj = *(const float4*)&xs[j * 128 + ln * 4];
                float4 vg = vv[j];
                part = fmaf(tanh_fast(xj.x + c.x), vg.x, part);
                part = fmaf(tanh_fast(xj.y + c.y), vg.y, part);
                part = fmaf(tanh_fast(xj.z + c.z), vg.z, part);
                part = fmaf(tanh_fast(xj.w + c.w), vg.w, part);
            }
#pragma unroll
            for (int off = 16; off; off >>= 1)
                part += __shfl_xor_sync(0xffffffffu, part, off);

            if (ln == 0) g_score[rowbase + s_idx[k]] = part;
            float p = __expf(part);    // fixed reference M=0: |score| < 40
            l += p;
#pragma unroll
            for (int j = 0; j < 8; j++) {          // re-read row (LDS, no spill)
                float4 c = *(const float4*)&sp_[j * 128 + ln * 4];
                acc[j].x = fmaf(c.x, p, acc[j].x);
                acc[j].y = fmaf(c.y, p, acc[j].y);
                acc[j].z = fmaf(c.z, p, acc[j].z);
                acc[j].w = fmaf(c.w, p, acc[j].w);
            }
            issue_row(cb, k + 3 * NWARP, n, ring_u32 + slot * HH * 4, ln, s_idx);
            slot = (slot == RING_DEPTH - 1) ? 0 : slot + 1;
        }
        asm volatile("cp.async.wait_group 0;" ::: "memory");

        // ---- CTA combine: overlay acc onto ring smem, tree-reduce ----
        if (ln == 0) s_l[w] = l;
        __syncthreads();
        float* sout = ring;
#pragma unroll
        for (int j = 0; j < 8; j++)
            *(float4*)&sout[w * HH + j * 128 + ln * 4] = acc[j];
        __syncthreads();

        float L = 0.f;
#pragma unroll
        for (int i = 0; i < NWARP; i++) L += s_l[i];
        float sum0 = 0.f, sum1 = 0.f;
#pragma unroll
        for (int i = 0; i < NWARP; i++) {
            sum0 += sout[i * HH + t];
            sum1 += sout[i * HH + t + 512];
        }
        g_acc[(size_t)tile * HH + t]       = sum0;
        g_acc[(size_t)tile * HH + t + 512] = sum1;
        if (t == 0) g_l[tile] = L;

        // ---- last tile of this batch? finalize the batch here ----
        __threadfence();
        if (t == 0) {
            unsigned old = atomicAdd(&g_bdone[b], 1u);
            s_last = (old == SPLITS - 1);
        }
        __syncthreads();
        if (s_last) {
            float Lb = 0.f;
#pragma unroll
            for (int i = 0; i < SPLITS; i++) Lb += __ldcg(&g_l[b * SPLITS + i]);
            float invL = 1.0f / Lb;
#pragma unroll
            for (int r = 0; r < 2; r++) {
                int h = t + r * 512;
                float s = 0.f;
#pragma unroll
                for (int i = 0; i < SPLITS; i++)
                    s += __ldcg(&g_acc[(size_t)(b * SPLITS + i) * HH + h]);
                out_applied[b * HH + h] = s * invL;
            }
#pragma unroll
            for (int r = 0; r < 4; r++) {
                int si = t + r * 512;
                float sc = __ldcg(&g_score[b * SS + si]);  // -inf masked -> 0
                out_w[b * SS + si] = __expf(sc) * invL;
            }
        }
        // top-of-loop __syncthreads orders smem reuse for the next tile
    }
}

// ---------------- launch ----------------
extern "C" void kernel_launch(void* const* d_in, const int* in_sizes, int n_in,
                              void* d_out, int out_size) {
    const float* inp  = (const float*)d_in[0];
    // d_in[1] = hidden (unused by the reference computation)
    const float* ctx  = (const float*)d_in[2];
    const void*  mask = d_in[3];
    const float* Wm   = (const float*)d_in[4];
    const float* bias = (const float*)d_in[5];
    const float* v    = (const float*)d_in[6];
    float* out = (float*)d_out;

    const int dyn_smem = (HH + NWARP * RING_DEPTH * HH) * (int)sizeof(float); // 200704
    cudaFuncSetAttribute(pass1_kernel,
                         cudaFuncAttributeMaxDynamicSharedMemorySize, dyn_smem);

    prologue_kernel<<<320, 256>>>(inp, Wm, mask);
    xreduce_kernel<<<128, 128>>>(bias);
    pass1_kernel<<<152, 512, dyn_smem>>>(ctx, v, out, out + BB * HH);
}

// round 13
// speedup vs baseline: 1.2843x; 1.0640x over previous
#include <cuda_runtime.h>
#include <cstdint>
#include <cstddef>

#define BB 64
#define SS 2048
#define DIN 512
#define HH 1024
#define SPLITS 8                       // tiles per batch; 512 tiles total
#define NTILES (BB * SPLITS)
#define ROWS_PER_TILE (SS / SPLITS)    // 256
#define NWARP 16
#define RING_DEPTH 3
#define KSPLIT 16                      // gemm k-chunks
#define KC 32
#define HC 64

#define NEG_INF __int_as_float(0xff800000)

// packed f32x2 ops (ptxas never auto-fuses these; SASS FFMA2 path)
#define ADD2(out, a, b) \
    asm("add.rn.f32x2 %0, %1, %2;" : "=l"(out) : "l"(a), "l"(b))
#define FMA2(out, a, b, c) \
    asm("fma.rn.f32x2 %0, %1, %2, %3;" : "=l"(out) : "l"(a), "l"(b), "l"(c))
#define UNPACK2(lo, hi, in) \
    asm("mov.b64 {%0, %1}, %2;" : "=f"(lo), "=f"(hi) : "l"(in))
#define PACK_BCAST(out, s) \
    asm("mov.b64 %0, {%1, %1};" : "=l"(out) : "f"(s))

// ---------------- scratch (no allocations allowed) ----------------
__device__ __align__(16) float g_x[BB * HH];            // inp@W + b
__device__ __align__(16) float g_xpart[KSPLIT * BB * HH];
__device__ unsigned char  g_mask[BB * SS];              // canonical mask (1 = masked)
__device__ float          g_score[BB * SS];             // raw scores (-inf where masked)
__device__ __align__(16) float g_acc[NTILES * HH];      // tile partial weighted sums
__device__ float          g_l[NTILES];                  // tile partial sum-of-exp
__device__ unsigned       g_ticket;                     // persistent work queue
__device__ unsigned       g_bdone[BB];                  // per-batch tile completion

// ---------------- helpers ----------------
__device__ __forceinline__ float tanh_fast(float x) {
    float y;
    asm("tanh.approx.f32 %0, %1;" : "=f"(y) : "f"(x));
    return y;
}

// ---------------- kernel 0: gemm partials (256 CTAs) + mask (64 CTAs) -------
__global__ __launch_bounds__(256) void prologue_kernel(const float* __restrict__ inp,
                                                       const float* __restrict__ Wm,
                                                       const void*  __restrict__ mraw) {
    __shared__ float Ws[KC][HC];   // 8 KB
    __shared__ float Is[KC][BB];   // 8 KB (k-major)
    int t   = threadIdx.x;
    int blk = blockIdx.x;

    if (blk < 256) {                               // ---- GEMM partials ----
        int kc = blk >> 4, hcb = blk & 15;
        int k0 = kc * KC, h0 = hcb * HC;

        for (int i = t; i < KC * HC / 4; i += 256) {
            int k = i >> 4, hj = i & 15;
            *(float4*)&Ws[k][hj * 4] =
                *(const float4*)&Wm[(size_t)(k0 + k) * HH + h0 + hj * 4];
        }
        for (int i = t; i < BB * KC / 4; i += 256) {
            int b = i >> 3, j = i & 7;
            float4 p = *(const float4*)&inp[b * DIN + k0 + j * 4];
            Is[j * 4 + 0][b] = p.x;
            Is[j * 4 + 1][b] = p.y;
            Is[j * 4 + 2][b] = p.z;
            Is[j * 4 + 3][b] = p.w;
        }
        __syncthreads();

        int ty = t >> 4, tx = t & 15;          // 4 batches x 4 cols / thread
        float4 a0 = {0,0,0,0}, a1 = {0,0,0,0}, a2 = {0,0,0,0}, a3 = {0,0,0,0};
#pragma unroll 8
        for (int k = 0; k < KC; k++) {
            float4 ib = *(const float4*)&Is[k][ty * 4];
            float4 wv = *(const float4*)&Ws[k][tx * 4];
            a0.x = fmaf(ib.x, wv.x, a0.x); a0.y = fmaf(ib.x, wv.y, a0.y);
            a0.z = fmaf(ib.x, wv.z, a0.z); a0.w = fmaf(ib.x, wv.w, a0.w);
            a1.x = fmaf(ib.y, wv.x, a1.x); a1.y = fmaf(ib.y, wv.y, a1.y);
            a1.z = fmaf(ib.y, wv.z, a1.z); a1.w = fmaf(ib.y, wv.w, a1.w);
            a2.x = fmaf(ib.z, wv.x, a2.x); a2.y = fmaf(ib.z, wv.y, a2.y);
            a2.z = fmaf(ib.z, wv.z, a2.z); a2.w = fmaf(ib.z, wv.w, a2.w);
            a3.x = fmaf(ib.w, wv.x, a3.x); a3.y = fmaf(ib.w, wv.y, a3.y);
            a3.z = fmaf(ib.w, wv.z, a3.z); a3.w = fmaf(ib.w, wv.w, a3.w);
        }
        float* outb = g_xpart + (size_t)kc * (BB * HH) + h0 + tx * 4;
        *(float4*)&outb[(ty * 4 + 0) * HH] = a0;
        *(float4*)&outb[(ty * 4 + 1) * HH] = a1;
        *(float4*)&outb[(ty * 4 + 2) * HH] = a2;
        *(float4*)&outb[(ty * 4 + 3) * HH] = a3;
    } else {                                    // ---- mask canonicalize ----
        const unsigned* wds = (const unsigned*)mraw;
        int notInt = 0, notFloat = 0;
        for (int i = t; i < 1024; i += 256) {
            unsigned x = wds[i];
            notInt   |= (x > 1u);
            notFloat |= (x != 0u && x != 0x3F800000u);
        }
        notInt   = __syncthreads_or(notInt);
        notFloat = __syncthreads_or(notFloat);
        int mode = notInt ? (notFloat ? 2 : 1) : 0;  // 0:int32 1:float32 2:bytes

        int base = (blk - 256) * 2048;
        for (int i = base + t; i < base + 2048; i += 256) {
            unsigned char v;
            if (mode == 0)      v = (((const int*)mraw)[i] != 0);
            else if (mode == 1) v = (((const float*)mraw)[i] != 0.0f);
            else                v = (((const unsigned char*)mraw)[i] != 0);
            g_mask[i] = v;
        }
    }
}

// ---------------- kernel 1: reduce gemm partials + bias, reset counters -----
__global__ __launch_bounds__(128) void xreduce_kernel(const float* __restrict__ bias) {
    int i = blockIdx.x * 128 + threadIdx.x;     // float4 index, 16384 total
    if (i == 0) g_ticket = 0;
    if (i < BB) g_bdone[i] = 0;
    float4 s = *(const float4*)&bias[(i & 255) * 4];
    const float4* xp = (const float4*)g_xpart;
#pragma unroll
    for (int kc = 0; kc < KSPLIT; kc++) {
        float4 p = xp[kc * (BB * HH / 4) + i];
        s.x += p.x; s.y += p.y; s.z += p.z; s.w += p.w;
    }
    ((float4*)g_x)[i] = s;
}

// ---------------- kernel 2: fused scores+exp-sum+weighted sum+finalize ------
__device__ __forceinline__ void issue_row(const float* cb, int k, int n,
                                          unsigned slot_u32, int ln,
                                          const int* s_idx) {
    if (k < n) {
        const float* src = cb + (size_t)s_idx[k] * HH + ln * 4;
        unsigned dst = slot_u32 + ln * 16;
#pragma unroll
        for (int i = 0; i < 8; i++)
            asm volatile("cp.async.cg.shared.global [%0], [%1], 16;"
                         :: "r"(dst + i * 512), "l"(src + i * 128) : "memory");
    }
    asm volatile("cp.async.commit_group;" ::: "memory");
}

__global__ __launch_bounds__(512, 1) void pass1_kernel(const float* __restrict__ ctx,
                                                       const float* __restrict__ v,
                                                       float* __restrict__ out_applied,
                                                       float* __restrict__ out_w) {
    extern __shared__ float dsm[];
    float* xs   = dsm;                 // HH floats
    float* ring = dsm + HH;            // NWARP * RING_DEPTH * HH floats

    __shared__ int      s_idx[ROWS_PER_TILE];
    __shared__ int      s_wcnt[8];
    __shared__ float    s_l[NWARP];
    __shared__ unsigned s_tile;
    __shared__ int      s_last;

    int t  = threadIdx.x;
    int w  = t >> 5;
    int ln = t & 31;

    float4 vv[8];
    const float4* vr = (const float4*)v;
#pragma unroll
    for (int j = 0; j < 8; j++) vv[j] = __ldg(&vr[j * 32 + ln]);

    float* myring = ring + w * (RING_DEPTH * HH);
    unsigned ring_u32 = (unsigned)__cvta_generic_to_shared(myring);

    for (;;) {
        if (t == 0) s_tile = atomicAdd(&g_ticket, 1u);
        __syncthreads();               // also orders prior tile's smem reuse
        unsigned tile = s_tile;
        if (tile >= NTILES) break;

        int b  = tile >> 3;            // SPLITS = 8
        int sp = tile & (SPLITS - 1);
        int rowbase = b * SS + sp * ROWS_PER_TILE;

        xs[t]       = g_x[b * HH + t];
        xs[t + 512] = g_x[b * HH + 512 + t];

        // ---- compact unmasked row indices (deterministic order) ----
        unsigned char mk = 1;
        if (t < ROWS_PER_TILE) mk = g_mask[rowbase + t];
        unsigned bits = __ballot_sync(0xffffffffu, mk == 0);
        if (t < ROWS_PER_TILE && mk) g_score[rowbase + t] = NEG_INF;
        if (w < 8 && ln == 0) s_wcnt[w] = __popc(bits);
        __syncthreads();
        int n = 0;
#pragma unroll
        for (int i = 0; i < 8; i++) n += s_wcnt[i];
        if (t < ROWS_PER_TILE && !mk) {
            int basew = 0;
#pragma unroll
            for (int i = 0; i < 8; i++) if (i < w) basew += s_wcnt[i];
            s_idx[basew + __popc(bits & ((1u << ln) - 1u))] = t;
        }
        __syncthreads();

        // ---- per-warp row loop over compacted list (f32x2 packed math) ----
        unsigned long long acc2[16];
#pragma unroll
        for (int j = 0; j < 16; j++) acc2[j] = 0ULL;
        float l = 0.f;

        const float* cb = ctx + (size_t)rowbase * HH;
        issue_row(cb, w,             n, ring_u32,          ln, s_idx);
        issue_row(cb, w + NWARP,     n, ring_u32 + HH * 4, ln, s_idx);
        issue_row(cb, w + 2 * NWARP, n, ring_u32 + HH * 8, ln, s_idx);
        int slot = 0;
        for (int k = w; k < n; k += NWARP) {
            asm volatile("cp.async.wait_group 2;" ::: "memory");
            const float* sp_ = myring + slot * HH;

            float q0 = 0.f, q1 = 0.f, q2 = 0.f, q3 = 0.f;
#pragma unroll
            for (int j = 0; j < 8; j++) {
                ulonglong2 c2 = *(const ulonglong2*)&sp_[j * 128 + ln * 4];
                ulonglong2 x2 = *(const ulonglong2*)&xs[j * 128 + ln * 4];
                unsigned long long s01, s23;
                ADD2(s01, c2.x, x2.x);
                ADD2(s23, c2.y, x2.y);
                float e0, e1, e2, e3;
                UNPACK2(e0, e1, s01);
                UNPACK2(e2, e3, s23);
                float4 vg = vv[j];
                q0 = fmaf(tanh_fast(e0), vg.x, q0);
                q1 = fmaf(tanh_fast(e1), vg.y, q1);
                q2 = fmaf(tanh_fast(e2), vg.z, q2);
                q3 = fmaf(tanh_fast(e3), vg.w, q3);
            }
            float part = (q0 + q1) + (q2 + q3);
#pragma unroll
            for (int off = 16; off; off >>= 1)
                part += __shfl_xor_sync(0xffffffffu, part, off);

            if (ln == 0) g_score[rowbase + s_idx[k]] = part;
            float p = __expf(part);    // fixed reference M=0: |score| < 40
            l += p;
            unsigned long long pp;
            PACK_BCAST(pp, p);
#pragma unroll
            for (int j = 0; j < 8; j++) {          // packed fma: 3 instr/iter
                ulonglong2 c2 = *(const ulonglong2*)&sp_[j * 128 + ln * 4];
                FMA2(acc2[2 * j],     c2.x, pp, acc2[2 * j]);
                FMA2(acc2[2 * j + 1], c2.y, pp, acc2[2 * j + 1]);
            }
            issue_row(cb, k + 3 * NWARP, n, ring_u32 + slot * HH * 4, ln, s_idx);
            slot = (slot == RING_DEPTH - 1) ? 0 : slot + 1;
        }
        asm volatile("cp.async.wait_group 0;" ::: "memory");

        // ---- CTA combine: overlay acc onto ring smem, tree-reduce ----
        if (ln == 0) s_l[w] = l;
        __syncthreads();
        float* sout = ring;
#pragma unroll
        for (int j = 0; j < 8; j++)
            *(ulonglong2*)&sout[w * HH + j * 128 + ln * 4] =
                make_ulonglong2(acc2[2 * j], acc2[2 * j + 1]);
        __syncthreads();

        float L = 0.f;
#pragma unroll
        for (int i = 0; i < NWARP; i++) L += s_l[i];
        float sum0 = 0.f, sum1 = 0.f;
#pragma unroll
        for (int i = 0; i < NWARP; i++) {
            sum0 += sout[i * HH + t];
            sum1 += sout[i * HH + t + 512];
        }
        g_acc[(size_t)tile * HH + t]       = sum0;
        g_acc[(size_t)tile * HH + t + 512] = sum1;
        if (t == 0) g_l[tile] = L;

        // ---- last tile of this batch? finalize the batch here ----
        __threadfence();
        if (t == 0) {
            unsigned old = atomicAdd(&g_bdone[b], 1u);
            s_last = (old == SPLITS - 1);
        }
        __syncthreads();
        if (s_last) {
            float Lb = 0.f;
#pragma unroll
            for (int i = 0; i < SPLITS; i++) Lb += __ldcg(&g_l[b * SPLITS + i]);
            float invL = 1.0f / Lb;
#pragma unroll
            for (int r = 0; r < 2; r++) {
                int h = t + r * 512;
                float s = 0.f;
#pragma unroll
                for (int i = 0; i < SPLITS; i++)
                    s += __ldcg(&g_acc[(size_t)(b * SPLITS + i) * HH + h]);
                out_applied[b * HH + h] = s * invL;
            }
#pragma unroll
            for (int r = 0; r < 4; r++) {
                int si = t + r * 512;
                float sc = __ldcg(&g_score[b * SS + si]);  // -inf masked -> 0
                out_w[b * SS + si] = __expf(sc) * invL;
            }
        }
        // top-of-loop __syncthreads orders smem reuse for the next tile
    }
}

// ---------------- launch ----------------
extern "C" void kernel_launch(void* const* d_in, const int* in_sizes, int n_in,
                              void* d_out, int out_size) {
    const float* inp  = (const float*)d_in[0];
    // d_in[1] = hidden (unused by the reference computation)
    const float* ctx  = (const float*)d_in[2];
    const void*  mask = d_in[3];
    const float* Wm   = (const float*)d_in[4];
    const float* bias = (const float*)d_in[5];
    const float* v    = (const float*)d_in[6];
    float* out = (float*)d_out;

    const int dyn_smem = (HH + NWARP * RING_DEPTH * HH) * (int)sizeof(float); // 200704
    cudaFuncSetAttribute(pass1_kernel,
                         cudaFuncAttributeMaxDynamicSharedMemorySize, dyn_smem);

    prologue_kernel<<<320, 256>>>(inp, Wm, mask);
    xreduce_kernel<<<128, 128>>>(bias);
    pass1_kernel<<<152, 512, dyn_smem>>>(ctx, v, out, out + BB * HH);
}